// round 9
// baseline (speedup 1.0000x reference)
#include <cuda_runtime.h>
#include <cstdint>

// ---------------------------------------------------------------------------
// ValueNetwork forward. Dead-code-eliminated: mlp1/global/attn branch unused.
// Live: self6 = state[:,0,:6]; LSTM(64 steps, in=7, hid=50); MLP 56->150->100->100->1.
// R9: LSTM Layout-A GEMM: lane=(colgroup,row), 25 column-PAIRS per lane ->
//     exactly 200 gate cols (kills the 224-pad 12% FMA waste); weights stored
//     as packed f32x2 pairs (ulonglong2 loads, zero dup-MOVs for weights);
//     gates row-major in smem (conflict-free activation reads).
// ---------------------------------------------------------------------------

#define B_SIZE 8192
#define NSTEP  64
#define ROWB   832          // floats per batch row of state (64*13)
#define HID    50
#define KDIM   57           // 7 input + 50 hidden
#define GATE   200
#define WSTR   208          // per-k weight stride: 4 groups * 52 floats
#define THREADS 256
// LSTM per-warp regions
#define HXW_FL  (KDIM * 8)          // 456: hx[k][8 rows]
#define GR_STR  204                 // gates row stride (200 + pad)
#define GW_FL   (8 * GR_STR)        // 1632: gates[8 rows][204]
// MLP
#define TMLP   512
#define RPBM   64
#define RSTRM  66

typedef unsigned long long ull;

__device__ float g_hT[HID * B_SIZE];          // [u][b]: final hidden state

// ---- f32x2 helpers --------------------------------------------------------
__device__ __forceinline__ ull dup2(float v) {
    ull r; asm("mov.b64 %0, {%1, %1};" : "=l"(r) : "f"(v)); return r;
}
__device__ __forceinline__ void fma2(ull& d, ull a, ull b) {
    asm("fma.rn.f32x2 %0, %1, %2, %0;" : "+l"(d) : "l"(a), "l"(b));
}
__device__ __forceinline__ float2 unpk(ull v) {
    float2 f; asm("mov.b64 {%0, %1}, %2;" : "=f"(f.x), "=f"(f.y) : "l"(v)); return f;
}
// ---- MUFU.TANH activations -------------------------------------------------
__device__ __forceinline__ float tanh_a(float x) {
    float y; asm("tanh.approx.f32 %0, %1;" : "=f"(y) : "f"(x)); return y;
}
__device__ __forceinline__ float sig_a(float x) {      // 0.5*tanh(x/2)+0.5
    return fmaf(tanh_a(0.5f * x), 0.5f, 0.5f);
}

// ---------------------------------------------------------------------------
// LSTM: 128 blocks x 64 rows; each warp owns 8 batch rows end-to-end.
// Lane (cg = lane>>3, r = lane&7): gate cols [50cg, 50cg+50) of row r,
// held as 25 f32x2 accumulator pairs.
// smem: W[57][208] (4x52 col-pair groups) | bias[208] | per-warp hx[57][8]
//       | per-warp gates[8][204]
// ---------------------------------------------------------------------------
#define LSTM_SM_FLOATS (KDIM * WSTR + WSTR + 8 * (HXW_FL + GW_FL))
#define LSTM_SM_BYTES  (LSTM_SM_FLOATS * 4)

__global__ __launch_bounds__(THREADS, 1) void lstm_kernel(
    const float* __restrict__ state,
    const float* __restrict__ wih, const float* __restrict__ whh,
    const float* __restrict__ bih, const float* __restrict__ bhh)
{
    extern __shared__ float sm[];
    float* Wsh = sm;                                    // 57*208
    float* bsh = sm + KDIM * WSTR;                      // 208

    const int tid  = threadIdx.x;
    const int lane = tid & 31;
    const int warp = tid >> 5;
    const int cg   = lane >> 3;       // column group 0..3 (50 cols each)
    const int r    = lane & 7;        // row within warp

    float* hxw = sm + KDIM * WSTR + WSTR + warp * HXW_FL;        // [k][8]
    float* gw  = sm + KDIM * WSTR + WSTR + 8 * HXW_FL + warp * GW_FL; // [r][204]

    // weights: [k][cg*52 + w] = W[k][cg*50 + w] for w<50, else 0
    for (int idx = tid; idx < KDIM * WSTR; idx += THREADS) {
        int k = idx / WSTR, s = idx - k * WSTR;
        int g = s / 52, w = s - g * 52;
        int c = g * 50 + w;
        float v = 0.f;
        if (w < 50)
            v = (k < 7) ? wih[k * GATE + c] : whh[(k - 7) * GATE + c];
        Wsh[idx] = v;
    }
    // bias, same grouped layout
    for (int s = tid; s < WSTR; s += THREADS) {
        int g = s / 52, w = s - g * 52;
        bsh[s] = (w < 50) ? bih[g * 50 + w] + bhh[g * 50 + w] : 0.f;
    }

    // zero h rows of hx; c state lives in registers
    for (int i = lane; i < (KDIM - 7) * 8; i += 32) hxw[7 * 8 + i] = 0.f;
    float creg[13];
    #pragma unroll
    for (int i = 0; i < 13; ++i) creg[i] = 0.f;

    // x(0): warp's 8 rows x 7 dims (7 contiguous floats per (b,t) row)
    const int b0 = blockIdx.x * 64 + warp * 8;
    {
        int i0 = lane, i1 = lane + 32;
        int r0 = i0 / 7, k0 = i0 - r0 * 7;
        float x0 = state[(size_t)(b0 + r0) * ROWB + 6 + k0];
        float x1 = 0.f;
        int r1 = i1 / 7, k1 = i1 - r1 * 7;
        if (i1 < 56) x1 = state[(size_t)(b0 + r1) * ROWB + 6 + k1];
        hxw[k0 * 8 + r0] = x0;
        if (i1 < 56) hxw[k1 * 8 + r1] = x1;
    }
    __syncthreads();    // Wsh/bsh ready (only block-wide sync in the kernel)

    const int cg52 = cg * 52;
    // x gather coords (fixed per lane)
    const int i1ok = (lane + 32) < 56;
    const int xr0 = lane / 7,        xk0 = lane - xr0 * 7;
    const int xr1 = (lane + 32) / 7, xk1 = (lane + 32) - xr1 * 7;
    const float* xp0 = state + (size_t)(b0 + xr0) * ROWB + 6 + xk0;
    const float* xp1 = state + (size_t)(b0 + (i1ok ? xr1 : 0)) * ROWB + 6 + xk1;

    for (int t = 0; t < NSTEP; ++t) {
        // prefetch x(t+1): LDG latency hidden under the GEMM
        int t2 = (t < NSTEP - 1) ? t + 1 : t;
        float xv0 = xp0[t2 * 13];
        float xv1 = i1ok ? xp1[t2 * 13] : 0.f;

        // gates[r][50cg..50cg+49] = sum_k hx[k][r] * W[k][cols] + bias
        ull acc[25];
        {
            const ulonglong2* bp = (const ulonglong2*)(bsh + cg52);
            #pragma unroll
            for (int q = 0; q < 12; ++q) {
                ulonglong2 v = bp[q];
                acc[2 * q] = v.x; acc[2 * q + 1] = v.y;
            }
            acc[24] = *(const ull*)(bsh + cg52 + 48);
        }
        #pragma unroll 3
        for (int k = 0; k < KDIM; ++k) {
            ull hd = dup2(hxw[k * 8 + r]);
            const ulonglong2* wp = (const ulonglong2*)(Wsh + k * WSTR + cg52);
            #pragma unroll
            for (int q = 0; q < 12; ++q) {
                ulonglong2 wv = wp[q];
                fma2(acc[2 * q],     hd, wv.x);
                fma2(acc[2 * q + 1], hd, wv.y);
            }
            fma2(acc[24], hd, *(const ull*)(Wsh + k * WSTR + cg52 + 48));
        }
        // gates -> row-major smem [r][204]
        {
            float* gpr = gw + r * GR_STR + cg * 50;
            #pragma unroll
            for (int j = 0; j < 25; ++j)
                *(ull*)(gpr + 2 * j) = acc[j];
        }
        __syncwarp();   // gate stores & hx reads done

        // x(t+1) into hx rows 0..6
        hxw[xk0 * 8 + xr0] = xv0;
        if (i1ok) hxw[xk1 * 8 + xr1] = xv1;

        // activation: 50 units x 8 rows, c in regs, h -> hx (MUFU.TANH)
        #pragma unroll
        for (int i = 0; i < 13; ++i) {
            int idx = lane + 32 * i;
            if (idx < HID * 8) {
                int u = idx >> 3, rr = idx & 7;
                const float* gpr = gw + rr * GR_STR;
                float gi = gpr[u];
                float gf = gpr[50 + u];
                float gg = gpr[100 + u];
                float go = gpr[150 + u];
                float c = sig_a(gf) * creg[i] + sig_a(gi) * tanh_a(gg);
                creg[i] = c;
                hxw[(7 + u) * 8 + rr] = sig_a(go) * tanh_a(c);
            }
        }
        __syncwarp();   // h/x visible before next GEMM
    }

    // final h -> global [u][b]
    #pragma unroll
    for (int i = 0; i < 13; ++i) {
        int idx = lane + 32 * i;
        if (idx < HID * 8) {
            int u = idx >> 3, rr = idx & 7;
            g_hT[u * B_SIZE + b0 + rr] = hxw[(7 + u) * 8 + rr];
        }
    }
}

// ---------------------------------------------------------------------------
// MLP: 512 threads (16 warps x 4 rows = 64 rows/block, grid 128);
// 4 warps/SMSP hides LDS->FMA chains. acc[2][CP] (no spills).
// ---------------------------------------------------------------------------
template<int IN, int OUT, int LA, int CP>
__device__ __forceinline__ void mlp_layer(const float* __restrict__ Wsh,
                                          const float* __restrict__ Bsh,
                                          const float* __restrict__ Xsh,
                                          float* __restrict__ Ysh,
                                          int lane, int rb)
{
    ull acc[2][CP];
    const bool act = lane < LA;
    #pragma unroll
    for (int j = 0; j < CP; ++j) {
        ull bv = dup2(act ? Bsh[j * LA + lane] : 0.f);
        acc[0][j] = bv; acc[1][j] = bv;
    }
    #pragma unroll 2
    for (int k = 0; k < IN; ++k) {
        const float* xr = &Xsh[k * RSTRM + rb];
        ull h0 = *(const ull*)(xr);
        ull h1 = *(const ull*)(xr + 2);
        #pragma unroll
        for (int j = 0; j < CP; ++j) {
            ull w2 = dup2(act ? Wsh[k * OUT + j * LA + lane] : 0.f);
            fma2(acc[0][j], h0, w2);
            fma2(acc[1][j], h1, w2);
        }
    }
    if (act) {
        #pragma unroll
        for (int j = 0; j < CP; ++j) {
            int c = j * LA + lane;
            float* yp = &Ysh[c * RSTRM + rb];
            #pragma unroll
            for (int rp = 0; rp < 2; ++rp) {
                float2 v = unpk(acc[rp][j]);
                v.x = fmaxf(v.x, 0.f);
                v.y = fmaxf(v.y, 0.f);
                *(float2*)(yp + 2 * rp) = v;
            }
        }
    }
}

// 16B-aligned smem layout (all offsets multiples of 4 floats)
#define OFF_W1 0
#define OFF_B1 8400
#define OFF_W2 8552            // 8400 + 152
#define OFF_B2 23552           // + 15000
#define OFF_W3 23656           // + 104
#define OFF_B3 33656           // + 10000
#define OFF_W4 33760           // + 104
#define OFF_B4 33864           // + 104
#define OFF_X  33868           // + 4
#define OFF_Y  (OFF_X + 150 * RSTRM)
#define MLP_SM_FLOATS (OFF_Y + 150 * RSTRM)
#define MLP_SM_BYTES  (MLP_SM_FLOATS * 4)

__global__ __launch_bounds__(TMLP, 1) void mlp_kernel(
    const float* __restrict__ state,
    const float* __restrict__ w1, const float* __restrict__ b1,
    const float* __restrict__ w2, const float* __restrict__ b2,
    const float* __restrict__ w3, const float* __restrict__ b3,
    const float* __restrict__ w4, const float* __restrict__ b4,
    float* __restrict__ out)
{
    extern __shared__ float sm[];
    float* w1s = sm + OFF_W1;
    float* b1s = sm + OFF_B1;
    float* w2s = sm + OFF_W2;
    float* b2s = sm + OFF_B2;
    float* w3s = sm + OFF_W3;
    float* b3s = sm + OFF_B3;
    float* w4s = sm + OFF_W4;
    float* b4s = sm + OFF_B4;
    float* X   = sm + OFF_X;
    float* Y   = sm + OFF_Y;

    const int tid = threadIdx.x;
    const int b0  = blockIdx.x * RPBM;

    // vectorized weight loads (all dst offsets 16B-aligned)
    for (int i = tid; i < 2100; i += TMLP)
        ((float4*)w1s)[i] = ((const float4*)w1)[i];
    for (int i = tid; i < 3750; i += TMLP)
        ((float4*)w2s)[i] = ((const float4*)w2)[i];
    for (int i = tid; i < 2500; i += TMLP)
        ((float4*)w3s)[i] = ((const float4*)w3)[i];
    if (tid < 150) b1s[tid] = b1[tid];
    if (tid < 100) { b2s[tid] = b2[tid]; b3s[tid] = b3[tid]; w4s[tid] = w4[tid]; }
    if (tid == 0) b4s[0] = b4[0];
    // joint = [self6 | h]
    for (int idx = tid; idx < 56 * RPBM; idx += TMLP) {
        int r = idx & 63, k = idx >> 6;
        X[k * RSTRM + r] = (k < 6) ? state[(size_t)(b0 + r) * ROWB + k]
                                   : g_hT[(k - 6) * B_SIZE + b0 + r];
    }
    __syncthreads();

    const int lane = tid & 31;
    const int rb   = (tid >> 5) * 4;    // 16 warps * 4 rows = 64 rows

    mlp_layer<56, 150, 30, 5>(w1s, b1s, X, Y, lane, rb);
    __syncthreads();
    mlp_layer<150, 100, 25, 4>(w2s, b2s, Y, X, lane, rb);
    __syncthreads();
    mlp_layer<100, 100, 25, 4>(w3s, b3s, X, Y, lane, rb);
    __syncthreads();

    if (tid < RPBM) {
        float a0 = 0.f, a1 = 0.f, a2 = 0.f, a3 = 0.f;
        #pragma unroll 5
        for (int k = 0; k < 100; k += 4) {
            a0 += Y[k * RSTRM + tid]       * w4s[k];
            a1 += Y[(k + 1) * RSTRM + tid] * w4s[k + 1];
            a2 += Y[(k + 2) * RSTRM + tid] * w4s[k + 2];
            a3 += Y[(k + 3) * RSTRM + tid] * w4s[k + 3];
        }
        out[b0 + tid] = a0 + a1 + a2 + a3 + b4s[0];
    }
}

// ---------------------------------------------------------------------------
extern "C" void kernel_launch(void* const* d_in, const int* in_sizes, int n_in,
                              void* d_out, int out_size)
{
    (void)in_sizes; (void)n_in; (void)out_size;
    const float* state = (const float*)d_in[0];
    const float* wih   = (const float*)d_in[11];
    const float* whh   = (const float*)d_in[12];
    const float* bih   = (const float*)d_in[13];
    const float* bhh   = (const float*)d_in[14];
    const float* w1    = (const float*)d_in[15];
    const float* b1    = (const float*)d_in[16];
    const float* w2    = (const float*)d_in[17];
    const float* b2    = (const float*)d_in[18];
    const float* w3    = (const float*)d_in[19];
    const float* b3    = (const float*)d_in[20];
    const float* w4    = (const float*)d_in[21];
    const float* b4    = (const float*)d_in[22];
    float* out = (float*)d_out;

    cudaFuncSetAttribute(lstm_kernel, cudaFuncAttributeMaxDynamicSharedMemorySize, LSTM_SM_BYTES);
    cudaFuncSetAttribute(mlp_kernel,  cudaFuncAttributeMaxDynamicSharedMemorySize, MLP_SM_BYTES);

    lstm_kernel<<<B_SIZE / 64, THREADS, LSTM_SM_BYTES>>>(state, wih, whh, bih, bhh);
    mlp_kernel<<<B_SIZE / RPBM, TMLP, MLP_SM_BYTES>>>(state, w1, b1, w2, b2,
                                                      w3, b3, w4, b4, out);
}

// round 10
// speedup vs baseline: 1.0313x; 1.0313x over previous
#include <cuda_runtime.h>
#include <cstdint>

// ---------------------------------------------------------------------------
// ValueNetwork forward. Dead-code-eliminated: mlp1/global/attn branch unused.
// Live: self6 = state[:,0,:6]; LSTM(64 steps, in=7, hid=50); MLP 56->150->100->100->1.
// R10: Layout-A GEMM (25 FFMA2/k, exact 200 cols) + manual 1-deep software
//      pipeline of weight loads (R9 regressed because 13 LDS/k couldn't be
//      hoisted under pressure -> exposed LDS latency). Zero-padded k row
//      keeps the k+1 prefetch branch-free.
// ---------------------------------------------------------------------------

#define B_SIZE 8192
#define NSTEP  64
#define ROWB   832          // floats per batch row of state (64*13)
#define HID    50
#define KDIM   57           // 7 input + 50 hidden
#define GATE   200
#define WSTR   208          // per-k weight stride: 4 groups * 52 floats
#define THREADS 256
// LSTM per-warp regions
#define HXW_FL  (58 * 8)            // 464: hx[k][8 rows], row 57 = zero pad
#define GR_STR  204                 // gates row stride (200 + pad)
#define GW_FL   (8 * GR_STR)        // 1632: gates[8 rows][204]
// MLP
#define TMLP   512
#define RPBM   64
#define RSTRM  66

typedef unsigned long long ull;

__device__ float g_hT[HID * B_SIZE];          // [u][b]: final hidden state

// ---- f32x2 helpers --------------------------------------------------------
__device__ __forceinline__ ull dup2(float v) {
    ull r; asm("mov.b64 %0, {%1, %1};" : "=l"(r) : "f"(v)); return r;
}
__device__ __forceinline__ void fma2(ull& d, ull a, ull b) {
    asm("fma.rn.f32x2 %0, %1, %2, %0;" : "+l"(d) : "l"(a), "l"(b));
}
__device__ __forceinline__ float2 unpk(ull v) {
    float2 f; asm("mov.b64 {%0, %1}, %2;" : "=f"(f.x), "=f"(f.y) : "l"(v)); return f;
}
// ---- MUFU.TANH activations -------------------------------------------------
__device__ __forceinline__ float tanh_a(float x) {
    float y; asm("tanh.approx.f32 %0, %1;" : "=f"(y) : "f"(x)); return y;
}
__device__ __forceinline__ float sig_a(float x) {      // 0.5*tanh(x/2)+0.5
    return fmaf(tanh_a(0.5f * x), 0.5f, 0.5f);
}

// ---------------------------------------------------------------------------
// LSTM: 128 blocks x 64 rows; each warp owns 8 batch rows end-to-end.
// Lane (cg = lane>>3, r = lane&7): gate cols [50cg, 50cg+50) of row r,
// 25 f32x2 accumulators. Weight loads software-pipelined 1 k-iter deep.
// smem: W[58][208] (row 57 zero) | bias[208] | per-warp hx[58][8] (row 57
//       zero) | per-warp gates[8][204]
// ---------------------------------------------------------------------------
#define LSTM_SM_FLOATS (58 * WSTR + WSTR + 8 * (HXW_FL + GW_FL))
#define LSTM_SM_BYTES  (LSTM_SM_FLOATS * 4)

__global__ __launch_bounds__(THREADS, 1) void lstm_kernel(
    const float* __restrict__ state,
    const float* __restrict__ wih, const float* __restrict__ whh,
    const float* __restrict__ bih, const float* __restrict__ bhh)
{
    extern __shared__ float sm[];
    float* Wsh = sm;                                    // 58*208 (row 57 zero)
    float* bsh = sm + 58 * WSTR;                        // 208

    const int tid  = threadIdx.x;
    const int lane = tid & 31;
    const int warp = tid >> 5;
    const int cg   = lane >> 3;       // column group 0..3 (50 cols each)
    const int r    = lane & 7;        // row within warp

    float* hxw = sm + 58 * WSTR + WSTR + warp * HXW_FL;            // [k][8]
    float* gw  = sm + 58 * WSTR + WSTR + 8 * HXW_FL + warp * GW_FL; // [r][204]

    // weights: [k][cg*52 + w] = W[k][cg*50 + w] for w<50 & k<57, else 0
    for (int idx = tid; idx < 58 * WSTR; idx += THREADS) {
        int k = idx / WSTR, s = idx - k * WSTR;
        int g = s / 52, w = s - g * 52;
        int c = g * 50 + w;
        float v = 0.f;
        if (w < 50 && k < KDIM)
            v = (k < 7) ? wih[k * GATE + c] : whh[(k - 7) * GATE + c];
        Wsh[idx] = v;
    }
    // bias, same grouped layout
    for (int s = tid; s < WSTR; s += THREADS) {
        int g = s / 52, w = s - g * 52;
        bsh[s] = (w < 50) ? bih[g * 50 + w] + bhh[g * 50 + w] : 0.f;
    }

    // zero h rows of hx (incl. pad row 57); c state lives in registers
    for (int i = lane; i < (58 - 7) * 8; i += 32) hxw[7 * 8 + i] = 0.f;
    float creg[13];
    #pragma unroll
    for (int i = 0; i < 13; ++i) creg[i] = 0.f;

    // x(0): warp's 8 rows x 7 dims (7 contiguous floats per (b,t) row)
    const int b0 = blockIdx.x * 64 + warp * 8;
    {
        int i0 = lane, i1 = lane + 32;
        int r0 = i0 / 7, k0 = i0 - r0 * 7;
        float x0 = state[(size_t)(b0 + r0) * ROWB + 6 + k0];
        float x1 = 0.f;
        int r1 = i1 / 7, k1 = i1 - r1 * 7;
        if (i1 < 56) x1 = state[(size_t)(b0 + r1) * ROWB + 6 + k1];
        hxw[k0 * 8 + r0] = x0;
        if (i1 < 56) hxw[k1 * 8 + r1] = x1;
    }
    __syncthreads();    // Wsh/bsh ready (only block-wide sync in the kernel)

    const int cg52 = cg * 52;
    const float* wbase = Wsh + cg52;
    // x gather coords (fixed per lane)
    const int i1ok = (lane + 32) < 56;
    const int xr0 = lane / 7,        xk0 = lane - xr0 * 7;
    const int xr1 = (lane + 32) / 7, xk1 = (lane + 32) - xr1 * 7;
    const float* xp0 = state + (size_t)(b0 + xr0) * ROWB + 6 + xk0;
    const float* xp1 = state + (size_t)(b0 + (i1ok ? xr1 : 0)) * ROWB + 6 + xk1;

    for (int t = 0; t < NSTEP; ++t) {
        // prefetch x(t+1): LDG latency hidden under the GEMM
        int t2 = (t < NSTEP - 1) ? t + 1 : t;
        float xv0 = xp0[t2 * 13];
        float xv1 = i1ok ? xp1[t2 * 13] : 0.f;

        // gates[r][50cg..50cg+49] = sum_k hx[k][r] * W[k][cols] + bias
        ull acc[25];
        {
            const ulonglong2* bp = (const ulonglong2*)(bsh + cg52);
            #pragma unroll
            for (int q = 0; q < 12; ++q) {
                ulonglong2 v = bp[q];
                acc[2 * q] = v.x; acc[2 * q + 1] = v.y;
            }
            acc[24] = *(const ull*)(bsh + cg52 + 48);
        }
        // software pipeline: buf holds first half (cols 0..23) of row k
        ulonglong2 buf[6];
        {
            const ulonglong2* wp0 = (const ulonglong2*)(wbase);
            #pragma unroll
            for (int q = 0; q < 6; ++q) buf[q] = wp0[q];
        }
        float hcur = hxw[r];    // k=0
        #pragma unroll 1
        for (int k = 0; k < KDIM; ++k) {
            const float* wk = wbase + k * WSTR;
            // issue second-half loads of row k (consumed 12 FMAs below)
            const ulonglong2* wp = (const ulonglong2*)wk;
            ulonglong2 w6 = wp[6],  w7 = wp[7],  w8 = wp[8];
            ulonglong2 w9 = wp[9], w10 = wp[10], w11 = wp[11];
            ull wt = *(const ull*)(wk + 48);
            float hnext = hxw[(k + 1) * 8 + r];     // row 57 = zero pad
            ull hd = dup2(hcur);
            // first half: buf is preloaded and ready
            fma2(acc[0],  hd, buf[0].x); fma2(acc[1],  hd, buf[0].y);
            fma2(acc[2],  hd, buf[1].x); fma2(acc[3],  hd, buf[1].y);
            fma2(acc[4],  hd, buf[2].x); fma2(acc[5],  hd, buf[2].y);
            fma2(acc[6],  hd, buf[3].x); fma2(acc[7],  hd, buf[3].y);
            fma2(acc[8],  hd, buf[4].x); fma2(acc[9],  hd, buf[4].y);
            fma2(acc[10], hd, buf[5].x); fma2(acc[11], hd, buf[5].y);
            // prefetch first half of row k+1 (zero row for k=56)
            {
                const ulonglong2* wpn = (const ulonglong2*)(wk + WSTR);
                #pragma unroll
                for (int q = 0; q < 6; ++q) buf[q] = wpn[q];
            }
            // second half: w6..w11/wt issued ~36 cyc ago -> ready
            fma2(acc[12], hd, w6.x);  fma2(acc[13], hd, w6.y);
            fma2(acc[14], hd, w7.x);  fma2(acc[15], hd, w7.y);
            fma2(acc[16], hd, w8.x);  fma2(acc[17], hd, w8.y);
            fma2(acc[18], hd, w9.x);  fma2(acc[19], hd, w9.y);
            fma2(acc[20], hd, w10.x); fma2(acc[21], hd, w10.y);
            fma2(acc[22], hd, w11.x); fma2(acc[23], hd, w11.y);
            fma2(acc[24], hd, wt);
            hcur = hnext;
        }
        // gates -> row-major smem [r][204]
        {
            float* gpr = gw + r * GR_STR + cg * 50;
            #pragma unroll
            for (int j = 0; j < 25; ++j)
                *(ull*)(gpr + 2 * j) = acc[j];
        }
        __syncwarp();   // gate stores & hx reads done

        // x(t+1) into hx rows 0..6
        hxw[xk0 * 8 + xr0] = xv0;
        if (i1ok) hxw[xk1 * 8 + xr1] = xv1;

        // activation: 50 units x 8 rows, c in regs, h -> hx (MUFU.TANH)
        #pragma unroll
        for (int i = 0; i < 13; ++i) {
            int idx = lane + 32 * i;
            if (idx < HID * 8) {
                int u = idx >> 3, rr = idx & 7;
                const float* gpr = gw + rr * GR_STR;
                float gi = gpr[u];
                float gf = gpr[50 + u];
                float gg = gpr[100 + u];
                float go = gpr[150 + u];
                float c = sig_a(gf) * creg[i] + sig_a(gi) * tanh_a(gg);
                creg[i] = c;
                hxw[(7 + u) * 8 + rr] = sig_a(go) * tanh_a(c);
            }
        }
        __syncwarp();   // h/x visible before next GEMM
    }

    // final h -> global [u][b]
    #pragma unroll
    for (int i = 0; i < 13; ++i) {
        int idx = lane + 32 * i;
        if (idx < HID * 8) {
            int u = idx >> 3, rr = idx & 7;
            g_hT[u * B_SIZE + b0 + rr] = hxw[(7 + u) * 8 + rr];
        }
    }
}

// ---------------------------------------------------------------------------
// MLP: 512 threads (16 warps x 4 rows = 64 rows/block, grid 128);
// 4 warps/SMSP hides LDS->FMA chains. acc[2][CP] (no spills).
// ---------------------------------------------------------------------------
template<int IN, int OUT, int LA, int CP>
__device__ __forceinline__ void mlp_layer(const float* __restrict__ Wsh,
                                          const float* __restrict__ Bsh,
                                          const float* __restrict__ Xsh,
                                          float* __restrict__ Ysh,
                                          int lane, int rb)
{
    ull acc[2][CP];
    const bool act = lane < LA;
    #pragma unroll
    for (int j = 0; j < CP; ++j) {
        ull bv = dup2(act ? Bsh[j * LA + lane] : 0.f);
        acc[0][j] = bv; acc[1][j] = bv;
    }
    #pragma unroll 2
    for (int k = 0; k < IN; ++k) {
        const float* xr = &Xsh[k * RSTRM + rb];
        ull h0 = *(const ull*)(xr);
        ull h1 = *(const ull*)(xr + 2);
        #pragma unroll
        for (int j = 0; j < CP; ++j) {
            ull w2 = dup2(act ? Wsh[k * OUT + j * LA + lane] : 0.f);
            fma2(acc[0][j], h0, w2);
            fma2(acc[1][j], h1, w2);
        }
    }
    if (act) {
        #pragma unroll
        for (int j = 0; j < CP; ++j) {
            int c = j * LA + lane;
            float* yp = &Ysh[c * RSTRM + rb];
            #pragma unroll
            for (int rp = 0; rp < 2; ++rp) {
                float2 v = unpk(acc[rp][j]);
                v.x = fmaxf(v.x, 0.f);
                v.y = fmaxf(v.y, 0.f);
                *(float2*)(yp + 2 * rp) = v;
            }
        }
    }
}

// 16B-aligned smem layout (all offsets multiples of 4 floats)
#define OFF_W1 0
#define OFF_B1 8400
#define OFF_W2 8552            // 8400 + 152
#define OFF_B2 23552           // + 15000
#define OFF_W3 23656           // + 104
#define OFF_B3 33656           // + 10000
#define OFF_W4 33760           // + 104
#define OFF_B4 33864           // + 104
#define OFF_X  33868           // + 4
#define OFF_Y  (OFF_X + 150 * RSTRM)
#define MLP_SM_FLOATS (OFF_Y + 150 * RSTRM)
#define MLP_SM_BYTES  (MLP_SM_FLOATS * 4)

__global__ __launch_bounds__(TMLP, 1) void mlp_kernel(
    const float* __restrict__ state,
    const float* __restrict__ w1, const float* __restrict__ b1,
    const float* __restrict__ w2, const float* __restrict__ b2,
    const float* __restrict__ w3, const float* __restrict__ b3,
    const float* __restrict__ w4, const float* __restrict__ b4,
    float* __restrict__ out)
{
    extern __shared__ float sm[];
    float* w1s = sm + OFF_W1;
    float* b1s = sm + OFF_B1;
    float* w2s = sm + OFF_W2;
    float* b2s = sm + OFF_B2;
    float* w3s = sm + OFF_W3;
    float* b3s = sm + OFF_B3;
    float* w4s = sm + OFF_W4;
    float* b4s = sm + OFF_B4;
    float* X   = sm + OFF_X;
    float* Y   = sm + OFF_Y;

    const int tid = threadIdx.x;
    const int b0  = blockIdx.x * RPBM;

    // vectorized weight loads (all dst offsets 16B-aligned)
    for (int i = tid; i < 2100; i += TMLP)
        ((float4*)w1s)[i] = ((const float4*)w1)[i];
    for (int i = tid; i < 3750; i += TMLP)
        ((float4*)w2s)[i] = ((const float4*)w2)[i];
    for (int i = tid; i < 2500; i += TMLP)
        ((float4*)w3s)[i] = ((const float4*)w3)[i];
    if (tid < 150) b1s[tid] = b1[tid];
    if (tid < 100) { b2s[tid] = b2[tid]; b3s[tid] = b3[tid]; w4s[tid] = w4[tid]; }
    if (tid == 0) b4s[0] = b4[0];
    // joint = [self6 | h]
    for (int idx = tid; idx < 56 * RPBM; idx += TMLP) {
        int r = idx & 63, k = idx >> 6;
        X[k * RSTRM + r] = (k < 6) ? state[(size_t)(b0 + r) * ROWB + k]
                                   : g_hT[(k - 6) * B_SIZE + b0 + r];
    }
    __syncthreads();

    const int lane = tid & 31;
    const int rb   = (tid >> 5) * 4;    // 16 warps * 4 rows = 64 rows

    mlp_layer<56, 150, 30, 5>(w1s, b1s, X, Y, lane, rb);
    __syncthreads();
    mlp_layer<150, 100, 25, 4>(w2s, b2s, Y, X, lane, rb);
    __syncthreads();
    mlp_layer<100, 100, 25, 4>(w3s, b3s, X, Y, lane, rb);
    __syncthreads();

    if (tid < RPBM) {
        float a0 = 0.f, a1 = 0.f, a2 = 0.f, a3 = 0.f;
        #pragma unroll 5
        for (int k = 0; k < 100; k += 4) {
            a0 += Y[k * RSTRM + tid]       * w4s[k];
            a1 += Y[(k + 1) * RSTRM + tid] * w4s[k + 1];
            a2 += Y[(k + 2) * RSTRM + tid] * w4s[k + 2];
            a3 += Y[(k + 3) * RSTRM + tid] * w4s[k + 3];
        }
        out[b0 + tid] = a0 + a1 + a2 + a3 + b4s[0];
    }
}

// ---------------------------------------------------------------------------
extern "C" void kernel_launch(void* const* d_in, const int* in_sizes, int n_in,
                              void* d_out, int out_size)
{
    (void)in_sizes; (void)n_in; (void)out_size;
    const float* state = (const float*)d_in[0];
    const float* wih   = (const float*)d_in[11];
    const float* whh   = (const float*)d_in[12];
    const float* bih   = (const float*)d_in[13];
    const float* bhh   = (const float*)d_in[14];
    const float* w1    = (const float*)d_in[15];
    const float* b1    = (const float*)d_in[16];
    const float* w2    = (const float*)d_in[17];
    const float* b2    = (const float*)d_in[18];
    const float* w3    = (const float*)d_in[19];
    const float* b3    = (const float*)d_in[20];
    const float* w4    = (const float*)d_in[21];
    const float* b4    = (const float*)d_in[22];
    float* out = (float*)d_out;

    cudaFuncSetAttribute(lstm_kernel, cudaFuncAttributeMaxDynamicSharedMemorySize, LSTM_SM_BYTES);
    cudaFuncSetAttribute(mlp_kernel,  cudaFuncAttributeMaxDynamicSharedMemorySize, MLP_SM_BYTES);

    lstm_kernel<<<B_SIZE / 64, THREADS, LSTM_SM_BYTES>>>(state, wih, whh, bih, bhh);
    mlp_kernel<<<B_SIZE / RPBM, TMLP, MLP_SM_BYTES>>>(state, w1, b1, w2, b2,
                                                      w3, b3, w4, b4, out);
}

// round 11
// speedup vs baseline: 1.2209x; 1.1838x over previous
#include <cuda_runtime.h>
#include <cstdint>

// ---------------------------------------------------------------------------
// ValueNetwork forward. Dead-code-eliminated: mlp1/global/attn branch unused.
// Live: self6 = state[:,0,:6]; LSTM(64 steps, in=7, hid=50); MLP 56->150->100->100->1.
// R11: GEMM reverted to R8 form (Layout-A abandoned: 2 rounds of evidence).
//      New: x-part (k=0..6) of step t+1's GEMM interleaved with step t's
//      activation (MUFU hides under FMA); warp-independent MLP (no block
//      barriers, warp-private activation buffers).
// ---------------------------------------------------------------------------

#define B_SIZE 8192
#define NSTEP  64
#define ROWB   832          // floats per batch row of state (64*13)
#define HID    50
#define KDIM   57           // 7 input + 50 hidden
#define GATE   200
#define WSTR   256          // per-k weight stride (32 lanes * 8 slots, 7 used)
#define THREADS 256
// LSTM per-warp regions
#define HXW_FL  (KDIM * 8)          // 456: hx[k][8 rows]
#define GW_STR  9                   // gate col stride (odd -> conflict-free STS.32)
#define GW_FL   (GATE * GW_STR)     // 1800
// MLP
#define TMLP   512
#define RPBM   64

typedef unsigned long long ull;

__device__ float g_hT[HID * B_SIZE];          // [u][b]: final hidden state

// ---- f32x2 helpers --------------------------------------------------------
__device__ __forceinline__ ull dup2(float v) {
    ull r; asm("mov.b64 %0, {%1, %1};" : "=l"(r) : "f"(v)); return r;
}
__device__ __forceinline__ void fma2(ull& d, ull a, ull b) {
    asm("fma.rn.f32x2 %0, %1, %2, %0;" : "+l"(d) : "l"(a), "l"(b));
}
__device__ __forceinline__ float2 unpk(ull v) {
    float2 f; asm("mov.b64 {%0, %1}, %2;" : "=f"(f.x), "=f"(f.y) : "l"(v)); return f;
}
// ---- MUFU.TANH activations -------------------------------------------------
__device__ __forceinline__ float tanh_a(float x) {
    float y; asm("tanh.approx.f32 %0, %1;" : "=f"(y) : "f"(x)); return y;
}
__device__ __forceinline__ float sig_a(float x) {      // 0.5*tanh(x/2)+0.5
    return fmaf(tanh_a(0.5f * x), 0.5f, 0.5f);
}

// ---------------------------------------------------------------------------
// LSTM: 128 blocks x 64 rows; each warp owns 8 batch rows end-to-end
// (no inter-warp dependency; syncwarp only). Per step:
//   [h-part GEMM k=7..56] [gate store] [x stage] [x-part GEMM(t+1) + act(t)]
// smem: W[57][256] shared | per-warp hx[57][8] | per-warp gates[200][9]
// ---------------------------------------------------------------------------
#define LSTM_SM_FLOATS (KDIM * WSTR + 8 * (HXW_FL + GW_FL))
#define LSTM_SM_BYTES  (LSTM_SM_FLOATS * 4)

__global__ __launch_bounds__(THREADS, 1) void lstm_kernel(
    const float* __restrict__ state,
    const float* __restrict__ wih, const float* __restrict__ whh,
    const float* __restrict__ bih, const float* __restrict__ bhh)
{
    extern __shared__ float sm[];
    float* Wsh = sm;                                    // 57*256

    const int tid  = threadIdx.x;
    const int lane = tid & 31;
    const int warp = tid >> 5;

    float* hxw = sm + KDIM * WSTR + warp * HXW_FL;      // [k][8]
    float* gw  = sm + KDIM * WSTR + 8 * HXW_FL + warp * GW_FL;  // [c][9]

    // weights: gate col 7*l+j at slot (k, 8*l+j); j==7 & c>=200 zero-padded
    for (int idx = tid; idx < KDIM * WSTR; idx += THREADS) {
        int k = idx >> 8, s = idx & 255, l = s >> 3, j = s & 7;
        int c = l * 7 + j;
        float v = 0.f;
        if (j < 7 && c < GATE)
            v = (k < 7) ? wih[k * GATE + c] : whh[(k - 7) * GATE + c];
        Wsh[idx] = v;
    }

    // biases straight into registers (cols lane*7+j)
    ull bdup[7];
    #pragma unroll
    for (int j = 0; j < 7; ++j) {
        int c = lane * 7 + j;
        bdup[j] = dup2(c < GATE ? bih[c] + bhh[c] : 0.f);
    }

    // zero h rows of hx; c state lives in registers
    for (int i = lane; i < (KDIM - 7) * 8; i += 32) hxw[7 * 8 + i] = 0.f;
    float creg[13];
    #pragma unroll
    for (int i = 0; i < 13; ++i) creg[i] = 0.f;

    // x(0): warp's 8 rows x 7 dims (7 contiguous floats per (b,t) row)
    const int b0 = blockIdx.x * 64 + warp * 8;
    {
        int i0 = lane, i1 = lane + 32;
        int r0 = i0 / 7, k0 = i0 - r0 * 7;
        float x0 = state[(size_t)(b0 + r0) * ROWB + 6 + k0];
        float x1 = 0.f;
        int r1 = i1 / 7, k1 = i1 - r1 * 7;
        if (i1 < 56) x1 = state[(size_t)(b0 + r1) * ROWB + 6 + k1];
        hxw[k0 * 8 + r0] = x0;
        if (i1 < 56) hxw[k1 * 8 + r1] = x1;
    }
    __syncthreads();    // Wsh ready (only block-wide sync in the kernel)

    const float* wl = Wsh + (lane << 3);
    // x gather coords (fixed per lane)
    const int i1ok = (lane + 32) < 56;
    const int xr0 = lane / 7,        xk0 = lane - xr0 * 7;
    const int xr1 = (lane + 32) / 7, xk1 = (lane + 32) - xr1 * 7;
    const float* xp0 = state + (size_t)(b0 + xr0) * ROWB + 6 + xk0;
    const float* xp1 = state + (size_t)(b0 + (i1ok ? xr1 : 0)) * ROWB + 6 + xk1;

    ull acc[4][7];

    // GEMM k-iteration body (R8 form: 2x LDS.128 w, 4x LDS.64 h, 28 FFMA2)
    #define GEMM_K(k)                                                     \
        {                                                                 \
            const float* hb = hxw + (k) * 8;                              \
            ull h0 = *(const ull*)(hb);                                   \
            ull h1 = *(const ull*)(hb + 2);                               \
            ull h2 = *(const ull*)(hb + 4);                               \
            ull h3 = *(const ull*)(hb + 6);                               \
            float4 wa = *(const float4*)(wl + ((k) << 8));                \
            float4 wb = *(const float4*)(wl + ((k) << 8) + 4);            \
            float w[7] = {wa.x, wa.y, wa.z, wa.w, wb.x, wb.y, wb.z};      \
            _Pragma("unroll")                                             \
            for (int j = 0; j < 7; ++j) {                                 \
                ull w2 = dup2(w[j]);                                      \
                fma2(acc[0][j], h0, w2);                                  \
                fma2(acc[1][j], h1, w2);                                  \
                fma2(acc[2][j], h2, w2);                                  \
                fma2(acc[3][j], h3, w2);                                  \
            }                                                             \
        }

    // pre-loop: bias init + x-part for t=0
    #pragma unroll
    for (int j = 0; j < 7; ++j) {
        acc[0][j] = bdup[j]; acc[1][j] = bdup[j];
        acc[2][j] = bdup[j]; acc[3][j] = bdup[j];
    }
    #pragma unroll
    for (int k = 0; k < 7; ++k) GEMM_K(k);

    for (int t = 0; t < NSTEP; ++t) {
        // prefetch x(t+1): LDG latency hidden under the h-part GEMM
        int t2 = (t < NSTEP - 1) ? t + 1 : t;
        float xv0 = xp0[t2 * 13];
        float xv1 = i1ok ? xp1[t2 * 13] : 0.f;

        // h-part GEMM: k = 7..56 (h(t), zero at t=0)
        #pragma unroll 5
        for (int k = 7; k < KDIM; ++k) GEMM_K(k);

        // spill gates to warp-private smem (stride 9 -> conflict-free)
        #pragma unroll
        for (int j = 0; j < 7; ++j) {
            int c = lane * 7 + j;
            if (c < GATE) {
                float* gp = gw + c * GW_STR;
                #pragma unroll
                for (int p = 0; p < 4; ++p) {
                    float2 v = unpk(acc[p][j]);
                    gp[2 * p] = v.x; gp[2 * p + 1] = v.y;
                }
            }
        }
        __syncwarp();   // gate stores & hx row 0..6 reads done

        // stage x(t+1) into hx rows 0..6
        hxw[xk0 * 8 + xr0] = xv0;
        if (i1ok) hxw[xk1 * 8 + xr1] = xv1;
        __syncwarp();   // x visible to x-part reads below

        // --- one barrier region: x-part GEMM(t+1) [FMA pipe] and
        //     activation(t) [MUFU pipe] are independent -> ptxas overlaps ---
        #pragma unroll
        for (int j = 0; j < 7; ++j) {
            acc[0][j] = bdup[j]; acc[1][j] = bdup[j];
            acc[2][j] = bdup[j]; acc[3][j] = bdup[j];
        }
        #pragma unroll
        for (int k = 0; k < 7; ++k) GEMM_K(k);

        // activation: 50 units x 8 rows, c in regs, h -> hx (MUFU.TANH)
        #pragma unroll
        for (int i = 0; i < 13; ++i) {
            int idx = lane + 32 * i;
            if (idx < HID * 8) {
                int u = idx >> 3, rr = idx & 7;
                float gi = gw[u * GW_STR + rr];
                float gf = gw[(HID + u) * GW_STR + rr];
                float gg = gw[(2 * HID + u) * GW_STR + rr];
                float go = gw[(3 * HID + u) * GW_STR + rr];
                float c = sig_a(gf) * creg[i] + sig_a(gi) * tanh_a(gg);
                creg[i] = c;
                hxw[(7 + u) * 8 + rr] = sig_a(go) * tanh_a(c);
            }
        }
        __syncwarp();   // h visible before next h-part GEMM
    }
    #undef GEMM_K

    // final h -> global [u][b]
    #pragma unroll
    for (int i = 0; i < 13; ++i) {
        int idx = lane + 32 * i;
        if (idx < HID * 8) {
            int u = idx >> 3, rr = idx & 7;
            g_hT[u * B_SIZE + b0 + rr] = hxw[(7 + u) * 8 + rr];
        }
    }
}

// ---------------------------------------------------------------------------
// MLP: warp-independent. 512 threads = 16 warps x 4 rows = 64 rows/block,
// grid 128. Each warp runs all 4 layers on its own rows with warp-private
// X/Y buffers (stride 4) -- no block barriers after weight staging.
// ---------------------------------------------------------------------------
template<int IN, int OUT, int LA, int CP>
__device__ __forceinline__ void mlp_layer_w(const float* __restrict__ Wsh,
                                            const float* __restrict__ Bsh,
                                            const float* __restrict__ Xw,
                                            float* __restrict__ Yw, int lane)
{
    ull acc[2][CP];
    const bool act = lane < LA;
    #pragma unroll
    for (int j = 0; j < CP; ++j) {
        ull bv = dup2(act ? Bsh[j * LA + lane] : 0.f);
        acc[0][j] = bv; acc[1][j] = bv;
    }
    #pragma unroll 2
    for (int k = 0; k < IN; ++k) {
        ull h0 = *(const ull*)(Xw + k * 4);        // broadcast within warp
        ull h1 = *(const ull*)(Xw + k * 4 + 2);
        #pragma unroll
        for (int j = 0; j < CP; ++j) {
            ull w2 = dup2(act ? Wsh[k * OUT + j * LA + lane] : 0.f);
            fma2(acc[0][j], h0, w2);
            fma2(acc[1][j], h1, w2);
        }
    }
    if (act) {
        #pragma unroll
        for (int j = 0; j < CP; ++j) {
            int c = j * LA + lane;
            #pragma unroll
            for (int rp = 0; rp < 2; ++rp) {
                float2 v = unpk(acc[rp][j]);
                v.x = fmaxf(v.x, 0.f);
                v.y = fmaxf(v.y, 0.f);
                *(float2*)(Yw + c * 4 + 2 * rp) = v;
            }
        }
    }
    __syncwarp();
}

// 16B-aligned smem layout (all offsets multiples of 4 floats)
#define OFF_W1 0
#define OFF_B1 8400
#define OFF_W2 8552            // 8400 + 152
#define OFF_B2 23552           // + 15000
#define OFF_W3 23656           // + 104
#define OFF_B3 33656           // + 10000
#define OFF_W4 33760           // + 104
#define OFF_B4 33864           // + 104
#define OFF_WB 33868           // + 4: per-warp buffers
#define WB_FL  832             // per-warp: X 224 | Y 600 | pad
#define MLP_SM_FLOATS (OFF_WB + 16 * WB_FL)
#define MLP_SM_BYTES  (MLP_SM_FLOATS * 4)

__global__ __launch_bounds__(TMLP, 1) void mlp_kernel(
    const float* __restrict__ state,
    const float* __restrict__ w1, const float* __restrict__ b1,
    const float* __restrict__ w2, const float* __restrict__ b2,
    const float* __restrict__ w3, const float* __restrict__ b3,
    const float* __restrict__ w4, const float* __restrict__ b4,
    float* __restrict__ out)
{
    extern __shared__ float sm[];
    float* w1s = sm + OFF_W1;
    float* b1s = sm + OFF_B1;
    float* w2s = sm + OFF_W2;
    float* b2s = sm + OFF_B2;
    float* w3s = sm + OFF_W3;
    float* b3s = sm + OFF_B3;
    float* w4s = sm + OFF_W4;
    float* b4s = sm + OFF_B4;

    const int tid  = threadIdx.x;
    const int lane = tid & 31;
    const int warp = tid >> 5;
    const int b0   = blockIdx.x * RPBM + warp * 4;     // warp's 4 rows

    float* Xw = sm + OFF_WB + warp * WB_FL;            // [56][4]
    float* Yw = Xw + 224;                              // [150][4]

    // vectorized weight loads (all dst offsets 16B-aligned)
    for (int i = tid; i < 2100; i += TMLP)
        ((float4*)w1s)[i] = ((const float4*)w1)[i];
    for (int i = tid; i < 3750; i += TMLP)
        ((float4*)w2s)[i] = ((const float4*)w2)[i];
    for (int i = tid; i < 2500; i += TMLP)
        ((float4*)w3s)[i] = ((const float4*)w3)[i];
    if (tid < 150) b1s[tid] = b1[tid];
    if (tid < 100) { b2s[tid] = b2[tid]; b3s[tid] = b3[tid]; w4s[tid] = w4[tid]; }
    if (tid == 0) b4s[0] = b4[0];

    // joint = [self6 | h] into warp-private X: 56*4 = 224 values, 7 per lane
    #pragma unroll
    for (int j = 0; j < 7; ++j) {
        int i = lane + 32 * j;
        int r = i & 3, k = i >> 2;
        Xw[k * 4 + r] = (k < 6) ? state[(size_t)(b0 + r) * ROWB + k]
                                : g_hT[(k - 6) * B_SIZE + b0 + r];
    }
    __syncthreads();    // weights + all X staged (single block barrier)

    mlp_layer_w<56, 150, 30, 5>(w1s, b1s, Xw, Yw, lane);
    mlp_layer_w<150, 100, 25, 4>(w2s, b2s, Yw, Xw, lane);
    mlp_layer_w<100, 100, 25, 4>(w3s, b3s, Xw, Yw, lane);

    // output: 4 rows x dot(Y[:,r], w4). 8 lanes per row, shfl reduce.
    {
        int r  = lane >> 3;         // 0..3
        int kk = lane & 7;          // 0..7
        float a = 0.f;
        #pragma unroll 4
        for (int k = kk; k < 100; k += 8)
            a = fmaf(Yw[k * 4 + r], w4s[k], a);
        a += __shfl_down_sync(0xFFFFFFFF, a, 4);
        a += __shfl_down_sync(0xFFFFFFFF, a, 2);
        a += __shfl_down_sync(0xFFFFFFFF, a, 1);
        if (kk == 0) out[b0 + r] = a + b4s[0];
    }
}

// ---------------------------------------------------------------------------
extern "C" void kernel_launch(void* const* d_in, const int* in_sizes, int n_in,
                              void* d_out, int out_size)
{
    (void)in_sizes; (void)n_in; (void)out_size;
    const float* state = (const float*)d_in[0];
    const float* wih   = (const float*)d_in[11];
    const float* whh   = (const float*)d_in[12];
    const float* bih   = (const float*)d_in[13];
    const float* bhh   = (const float*)d_in[14];
    const float* w1    = (const float*)d_in[15];
    const float* b1    = (const float*)d_in[16];
    const float* w2    = (const float*)d_in[17];
    const float* b2    = (const float*)d_in[18];
    const float* w3    = (const float*)d_in[19];
    const float* b3    = (const float*)d_in[20];
    const float* w4    = (const float*)d_in[21];
    const float* b4    = (const float*)d_in[22];
    float* out = (float*)d_out;

    cudaFuncSetAttribute(lstm_kernel, cudaFuncAttributeMaxDynamicSharedMemorySize, LSTM_SM_BYTES);
    cudaFuncSetAttribute(mlp_kernel,  cudaFuncAttributeMaxDynamicSharedMemorySize, MLP_SM_BYTES);

    lstm_kernel<<<B_SIZE / 64, THREADS, LSTM_SM_BYTES>>>(state, wih, whh, bih, bhh);
    mlp_kernel<<<B_SIZE / RPBM, TMLP, MLP_SM_BYTES>>>(state, w1, b1, w2, b2,
                                                      w3, b3, w4, b4, out);
}

// round 12
// speedup vs baseline: 1.2731x; 1.0428x over previous
#include <cuda_runtime.h>
#include <cstdint>

// ---------------------------------------------------------------------------
// ValueNetwork forward. Dead-code-eliminated: mlp1/global/attn branch unused.
// Live: self6 = state[:,0,:6]; LSTM(64 steps, in=7, hid=50); MLP 56->150->100->100->1.
// R12: single fused kernel. LSTM at 7 rows/warp, grid 147 (perfect SMSP
//      balance: 14 rows/SMSP vs 16; -8.3% FMA floor; 147/148 SMs).
//      MLP fused as phase B: per-warp X buffers in disjoint smem, weights
//      staged over the dead LSTM smem, warp-independent layers.
// ---------------------------------------------------------------------------

#define B_SIZE 8192
#define NSTEP  64
#define ROWB   832          // floats per batch row of state (64*13)
#define HID    50
#define KDIM   57           // 7 input + 50 hidden
#define GATE   200
#define WSTR   256          // per-k weight stride (32 lanes * 8 slots, 7 used)
#define THREADS 256
#define RPW    7            // batch rows per warp
#define RPB    56           // rows per block (8 warps * 7)
#define GRID   147          // ceil(8192/56)
// LSTM per-warp regions
#define HXW_FL  (KDIM * 8)          // 456: hx[k][8 slots] (slot 7 unused)
#define GW_STR  9                   // gate col stride (odd -> conflict-free)
#define GW_FL   (GATE * GW_STR)     // 1800

typedef unsigned long long ull;

// ---- f32x2 helpers --------------------------------------------------------
__device__ __forceinline__ ull dup2(float v) {
    ull r; asm("mov.b64 %0, {%1, %1};" : "=l"(r) : "f"(v)); return r;
}
__device__ __forceinline__ void fma2(ull& d, ull a, ull b) {
    asm("fma.rn.f32x2 %0, %1, %2, %0;" : "+l"(d) : "l"(a), "l"(b));
}
__device__ __forceinline__ float2 unpk(ull v) {
    float2 f; asm("mov.b64 {%0, %1}, %2;" : "=f"(f.x), "=f"(f.y) : "l"(v)); return f;
}
// ---- MUFU.TANH activations -------------------------------------------------
__device__ __forceinline__ float tanh_a(float x) {
    float y; asm("tanh.approx.f32 %0, %1;" : "=f"(y) : "f"(x)); return y;
}
__device__ __forceinline__ float sig_a(float x) {      // 0.5*tanh(x/2)+0.5
    return fmaf(tanh_a(0.5f * x), 0.5f, 0.5f);
}

// ---- smem layout ------------------------------------------------------------
// Phase A (LSTM): [0, 32640) floats:
//   Wsh 57*256 | per-warp hx[57][8] | per-warp gates[200][9]
// Phase B (MLP) overwrites [0, 33866):
//   w1 8400 | b1 152 | w2 15000 | b2 104 | w3 10000 | b3 104 | w4 104 | b4 4
// Per-warp X/Y buffers live at [33868, 47052) in BOTH phases (disjoint).
#define OFF_W1 0
#define OFF_B1 8400
#define OFF_W2 8552
#define OFF_B2 23552
#define OFF_W3 23656
#define OFF_B3 33656
#define OFF_W4 33760
#define OFF_B4 33864
#define OFF_WB 33868
#define WB_FL  1648              // per-warp: X[56][8]=448 | Y[150][8]=1200
#define SM_FLOATS (OFF_WB + 8 * WB_FL)
#define SM_BYTES  (SM_FLOATS * 4)

// MLP layer on warp-private buffers (stride-8 rows, 4 row-pairs incl pad row 7)
template<int IN, int OUT, int LA, int CP>
__device__ __forceinline__ void mlp_layer8(const float* __restrict__ Wsh,
                                           const float* __restrict__ Bsh,
                                           const float* __restrict__ Xw,
                                           float* __restrict__ Yw, int lane)
{
    ull acc[4][CP];
    const bool act = lane < LA;
    #pragma unroll
    for (int j = 0; j < CP; ++j) {
        ull bv = dup2(act ? Bsh[j * LA + lane] : 0.f);
        acc[0][j] = bv; acc[1][j] = bv; acc[2][j] = bv; acc[3][j] = bv;
    }
    #pragma unroll 2
    for (int k = 0; k < IN; ++k) {
        const float* xr = Xw + k * 8;
        ull h0 = *(const ull*)(xr);
        ull h1 = *(const ull*)(xr + 2);
        ull h2 = *(const ull*)(xr + 4);
        ull h3 = *(const ull*)(xr + 6);
        #pragma unroll
        for (int j = 0; j < CP; ++j) {
            ull w2 = dup2(act ? Wsh[k * OUT + j * LA + lane] : 0.f);
            fma2(acc[0][j], h0, w2);
            fma2(acc[1][j], h1, w2);
            fma2(acc[2][j], h2, w2);
            fma2(acc[3][j], h3, w2);
        }
    }
    if (act) {
        #pragma unroll
        for (int j = 0; j < CP; ++j) {
            int c = j * LA + lane;
            float* yp = Yw + c * 8;
            #pragma unroll
            for (int rp = 0; rp < 4; ++rp) {
                float2 v = unpk(acc[rp][j]);
                v.x = fmaxf(v.x, 0.f);
                v.y = fmaxf(v.y, 0.f);
                *(float2*)(yp + 2 * rp) = v;
            }
        }
    }
    __syncwarp();
}

__global__ __launch_bounds__(THREADS, 1) void fused_kernel(
    const float* __restrict__ state,
    const float* __restrict__ wih, const float* __restrict__ whh,
    const float* __restrict__ bih, const float* __restrict__ bhh,
    const float* __restrict__ w1, const float* __restrict__ b1,
    const float* __restrict__ w2, const float* __restrict__ b2,
    const float* __restrict__ w3, const float* __restrict__ b3,
    const float* __restrict__ w4, const float* __restrict__ b4,
    float* __restrict__ out)
{
    extern __shared__ float sm[];
    float* Wsh = sm;                                    // 57*256

    const int tid  = threadIdx.x;
    const int lane = tid & 31;
    const int warp = tid >> 5;

    float* hxw = sm + KDIM * WSTR + warp * HXW_FL;      // [k][8]
    float* gw  = sm + KDIM * WSTR + 8 * HXW_FL + warp * GW_FL;  // [c][9]
    float* Xw  = sm + OFF_WB + warp * WB_FL;            // [56][8]
    float* Yw  = Xw + 448;                              // [150][8]

    const int b0 = blockIdx.x * RPB + warp * RPW;       // warp's 7 rows

    // ======================= Phase A: LSTM =================================
    // weights: gate col 7*l+j at slot (k, 8*l+j); j==7 & c>=200 zero-padded
    for (int idx = tid; idx < KDIM * WSTR; idx += THREADS) {
        int k = idx >> 8, s = idx & 255, l = s >> 3, j = s & 7;
        int c = l * 7 + j;
        float v = 0.f;
        if (j < 7 && c < GATE)
            v = (k < 7) ? wih[k * GATE + c] : whh[(k - 7) * GATE + c];
        Wsh[idx] = v;
    }

    // biases into registers (cols lane*7+j), dup + scalar forms
    ull bdup[7]; float bflt[7];
    #pragma unroll
    for (int j = 0; j < 7; ++j) {
        int c = lane * 7 + j;
        bflt[j] = (c < GATE) ? bih[c] + bhh[c] : 0.f;
        bdup[j] = dup2(bflt[j]);
    }

    // zero hx; c state lives in registers (7 rows * 50 units / 32 lanes -> 11)
    for (int i = lane; i < HXW_FL; i += 32) hxw[i] = 0.f;
    float creg[11];
    #pragma unroll
    for (int i = 0; i < 11; ++i) creg[i] = 0.f;

    // x gather coords: 49 values (7 rows x 7 dims), clamped batch rows
    const int xr0 = lane / 7,        xk0 = lane - xr0 * 7;          // idx 0..31
    const int xr1 = (lane + 32) / 7, xk1 = (lane + 32) - xr1 * 7;   // idx 32..48
    const int i1ok = (lane + 32) < 49;
    const int bR0 = min(b0 + xr0, B_SIZE - 1);
    const int bR1 = min(b0 + (i1ok ? xr1 : 0), B_SIZE - 1);
    const float* xp0 = state + (size_t)bR0 * ROWB + 6 + xk0;
    const float* xp1 = state + (size_t)bR1 * ROWB + 6 + xk1;

    // x(0)
    hxw[xk0 * 8 + xr0] = xp0[0];
    if (i1ok) hxw[xk1 * 8 + xr1] = xp1[0];
    __syncthreads();    // Wsh ready

    const float* wl = Wsh + (lane << 3);
    ull acc[3][7]; float accs[7];

    // 7-row GEMM body: rows (0,1),(2,3),(4,5) paired + row 6 scalar
    #define GEMM_K7(k)                                                    \
        {                                                                 \
            const float* hb = hxw + (k) * 8;                              \
            ull h0 = *(const ull*)(hb);                                   \
            ull h1 = *(const ull*)(hb + 2);                               \
            ull h2 = *(const ull*)(hb + 4);                               \
            float h6 = hb[6];                                             \
            float4 wa = *(const float4*)(wl + ((k) << 8));                \
            float4 wb = *(const float4*)(wl + ((k) << 8) + 4);            \
            float w[7] = {wa.x, wa.y, wa.z, wa.w, wb.x, wb.y, wb.z};      \
            _Pragma("unroll")                                             \
            for (int j = 0; j < 7; ++j) {                                 \
                ull w2 = dup2(w[j]);                                      \
                fma2(acc[0][j], h0, w2);                                  \
                fma2(acc[1][j], h1, w2);                                  \
                fma2(acc[2][j], h2, w2);                                  \
                accs[j] = fmaf(h6, w[j], accs[j]);                        \
            }                                                             \
        }

    // pre-loop: bias init + x-part for t=0
    #pragma unroll
    for (int j = 0; j < 7; ++j) {
        acc[0][j] = bdup[j]; acc[1][j] = bdup[j]; acc[2][j] = bdup[j];
        accs[j] = bflt[j];
    }
    #pragma unroll
    for (int k = 0; k < 7; ++k) GEMM_K7(k);

    for (int t = 0; t < NSTEP; ++t) {
        // prefetch x(t+1)
        int t2 = (t < NSTEP - 1) ? t + 1 : t;
        float xv0 = xp0[t2 * 13];
        float xv1 = i1ok ? xp1[t2 * 13] : 0.f;

        // h-part GEMM: k = 7..56
        #pragma unroll 5
        for (int k = 7; k < KDIM; ++k) GEMM_K7(k);

        // spill gates (float stores, stride 9 -> conflict-free)
        #pragma unroll
        for (int j = 0; j < 7; ++j) {
            int c = lane * 7 + j;
            if (c < GATE) {
                float* gp = gw + c * GW_STR;
                float2 v0 = unpk(acc[0][j]); gp[0] = v0.x; gp[1] = v0.y;
                float2 v1 = unpk(acc[1][j]); gp[2] = v1.x; gp[3] = v1.y;
                float2 v2 = unpk(acc[2][j]); gp[4] = v2.x; gp[5] = v2.y;
                gp[6] = accs[j];
            }
        }
        __syncwarp();   // gate stores & hx row reads done

        // stage x(t+1)
        hxw[xk0 * 8 + xr0] = xv0;
        if (i1ok) hxw[xk1 * 8 + xr1] = xv1;
        __syncwarp();

        // --- x-part GEMM(t+1) [FMA] + activation(t) [MUFU] overlap ---
        #pragma unroll
        for (int j = 0; j < 7; ++j) {
            acc[0][j] = bdup[j]; acc[1][j] = bdup[j]; acc[2][j] = bdup[j];
            accs[j] = bflt[j];
        }
        #pragma unroll
        for (int k = 0; k < 7; ++k) GEMM_K7(k);

        // activation: 50 units x 7 rows = 350, c in regs
        #pragma unroll
        for (int i = 0; i < 11; ++i) {
            int idx = lane + 32 * i;
            if (idx < HID * RPW) {
                int u = idx / 7, rr = idx - u * 7;
                float gi = gw[u * GW_STR + rr];
                float gf = gw[(HID + u) * GW_STR + rr];
                float gg = gw[(2 * HID + u) * GW_STR + rr];
                float go = gw[(3 * HID + u) * GW_STR + rr];
                float c = sig_a(gf) * creg[i] + sig_a(gi) * tanh_a(gg);
                creg[i] = c;
                hxw[(7 + u) * 8 + rr] = sig_a(go) * tanh_a(c);
            }
        }
        __syncwarp();   // h visible before next h-part GEMM
    }
    #undef GEMM_K7

    // ================== Phase A->B transition ==============================
    // Build warp-private X = [self6 | h] (rows 0..6, pad row 7) in the
    // disjoint Xw region; zero first.
    for (int i = lane; i < 448; i += 32) Xw[i] = 0.f;
    __syncwarp();
    // h rows from hxw (still intact)
    #pragma unroll
    for (int i = 0; i < 11; ++i) {
        int idx = lane + 32 * i;
        if (idx < HID * RPW) {
            int u = idx / 7, rr = idx - u * 7;
            Xw[(6 + u) * 8 + rr] = hxw[(7 + u) * 8 + rr];
        }
    }
    // self6: 42 values (7 rows x 6 dims), clamped rows
    {
        int idx0 = lane;                 // < 42 for all lanes 0..31
        int r0 = idx0 / 6, k0 = idx0 - r0 * 6;
        if (idx0 < 42)
            Xw[k0 * 8 + r0] = state[(size_t)min(b0 + r0, B_SIZE - 1) * ROWB + k0];
        int idx1 = lane + 32;
        int r1 = idx1 / 6, k1 = idx1 - r1 * 6;
        if (idx1 < 42)
            Xw[k1 * 8 + r1] = state[(size_t)min(b0 + r1, B_SIZE - 1) * ROWB + k1];
    }
    __syncthreads();    // everyone done with LSTM smem

    // stage MLP weights over the dead LSTM region
    float* w1s = sm + OFF_W1;
    float* b1s = sm + OFF_B1;
    float* w2s = sm + OFF_W2;
    float* b2s = sm + OFF_B2;
    float* w3s = sm + OFF_W3;
    float* b3s = sm + OFF_B3;
    float* w4s = sm + OFF_W4;
    float* b4s = sm + OFF_B4;
    for (int i = tid; i < 2100; i += THREADS)
        ((float4*)w1s)[i] = ((const float4*)w1)[i];
    for (int i = tid; i < 3750; i += THREADS)
        ((float4*)w2s)[i] = ((const float4*)w2)[i];
    for (int i = tid; i < 2500; i += THREADS)
        ((float4*)w3s)[i] = ((const float4*)w3)[i];
    if (tid < 150) b1s[tid] = b1[tid];
    if (tid < 100) { b2s[tid] = b2[tid]; b3s[tid] = b3[tid]; w4s[tid] = w4[tid]; }
    if (tid == 0) b4s[0] = b4[0];
    __syncthreads();    // weights visible

    // ======================= Phase B: MLP ==================================
    mlp_layer8<56, 150, 30, 5>(w1s, b1s, Xw, Yw, lane);
    mlp_layer8<150, 100, 25, 4>(w2s, b2s, Yw, Xw, lane);
    mlp_layer8<100, 100, 25, 4>(w3s, b3s, Xw, Yw, lane);

    // output: 8 rows (7 real), 4 lanes per row, shfl reduce
    {
        int r  = lane >> 2;          // 0..7
        int kk = lane & 3;           // 0..3
        float a = 0.f;
        #pragma unroll 5
        for (int k = kk; k < 100; k += 4)
            a = fmaf(Yw[k * 8 + r], w4s[k], a);
        a += __shfl_down_sync(0xFFFFFFFF, a, 2);
        a += __shfl_down_sync(0xFFFFFFFF, a, 1);
        if (kk == 0 && r < RPW && b0 + r < B_SIZE)
            out[b0 + r] = a + b4s[0];
    }
}

// ---------------------------------------------------------------------------
extern "C" void kernel_launch(void* const* d_in, const int* in_sizes, int n_in,
                              void* d_out, int out_size)
{
    (void)in_sizes; (void)n_in; (void)out_size;
    const float* state = (const float*)d_in[0];
    const float* wih   = (const float*)d_in[11];
    const float* whh   = (const float*)d_in[12];
    const float* bih   = (const float*)d_in[13];
    const float* bhh   = (const float*)d_in[14];
    const float* w1    = (const float*)d_in[15];
    const float* b1    = (const float*)d_in[16];
    const float* w2    = (const float*)d_in[17];
    const float* b2    = (const float*)d_in[18];
    const float* w3    = (const float*)d_in[19];
    const float* b3    = (const float*)d_in[20];
    const float* w4    = (const float*)d_in[21];
    const float* b4    = (const float*)d_in[22];
    float* out = (float*)d_out;

    cudaFuncSetAttribute(fused_kernel, cudaFuncAttributeMaxDynamicSharedMemorySize, SM_BYTES);

    fused_kernel<<<GRID, THREADS, SM_BYTES>>>(state, wih, whh, bih, bhh,
                                              w1, b1, w2, b2, w3, b3, w4, b4,
                                              out);
}